// round 17
// baseline (speedup 1.0000x reference)
#include <cuda_runtime.h>
#include <cuda_fp16.h>
#include <math.h>

// Problem constants
#define BT 512      // batch
#define IC 1152     // in capsules
#define DD 8        // in dim
#define OC 10       // out capsules
#define EC 16       // out dim
#define G  2        // batches per CTA
#define T  576      // threads per CTA (18 warps)
#define NW 18       // warps
#define NCH 8       // chunks of 144 rows
#define RPC 144     // rows per chunk
#define LOG2E 1.4426950408889634f

typedef unsigned long long u64;

// Reordered fp16 W: [o][c(8)][j(4)][slot(576)][8 halves]
// slot = rl*4+eg; j = d-pair {2j,2j+1}; 8 halves = (d=2j: e01,e23), (d=2j+1: e01,e23)
__device__ __align__(16) __half Wh[(size_t)OC * IC * DD * EC];
// fp16 x: [b][i][8 halves] (one uint4 per row)
__device__ __align__(16) __half Xh[(size_t)BT * IC * DD];

__global__ void prep_w(const float* __restrict__ W) {
    int t = blockIdx.x * blockDim.x + threadIdx.x;   // < 184320
    int slot = t % T;
    int r = t / T;
    int j = r & 3; r >>= 2;
    int c = r % NCH;
    int o = r / NCH;
    int i = c * RPC + (slot >> 2);
    int eg = slot & 3;
    const float4* src = (const float4*)(W + ((size_t)o * IC + i) * 128);
    float4 a = src[(2 * j) * 4 + eg];       // d = 2j,   e = eg*4..+3
    float4 b = src[(2 * j + 1) * 4 + eg];   // d = 2j+1, e = eg*4..+3
    __half2 h[4];
    h[0] = __floats2half2_rn(a.x, a.y);
    h[1] = __floats2half2_rn(a.z, a.w);
    h[2] = __floats2half2_rn(b.x, b.y);
    h[3] = __floats2half2_rn(b.z, b.w);
    ((uint4*)Wh)[t] = *(uint4*)h;
}

__global__ void prep_x(const float* __restrict__ x) {
    int t = blockIdx.x * blockDim.x + threadIdx.x;   // < BT*IC = 589824
    const float4* src = (const float4*)(x + (size_t)t * DD);
    float4 a = src[0], b = src[1];
    __half2 h[4];
    h[0] = __floats2half2_rn(a.x, a.y);   // (d0,d1)
    h[1] = __floats2half2_rn(a.z, a.w);   // (d2,d3)
    h[2] = __floats2half2_rn(b.x, b.y);   // (d4,d5)
    h[3] = __floats2half2_rn(b.z, b.w);   // (d6,d7)
    ((uint4*)Xh)[t] = *(uint4*)h;
}

// ---- packed fp32x2 helpers ----
__device__ __forceinline__ u64 pk2(float a, float b) {
    u64 r; asm("mov.b64 %0, {%1, %2};" : "=l"(r) : "f"(a), "f"(b)); return r;
}
__device__ __forceinline__ void fma2(u64& d, u64 a, u64 b) {
    asm("fma.rn.f32x2 %0, %1, %2, %3;" : "=l"(d) : "l"(a), "l"(b), "l"(d));
}
__device__ __forceinline__ u64 add2(u64 a, u64 b) {
    u64 r; asm("add.rn.f32x2 %0, %1, %2;" : "=l"(r) : "l"(a), "l"(b)); return r;
}
__device__ __forceinline__ float2 up2(u64 a) {
    float2 f; asm("mov.b64 {%0, %1}, %2;" : "=f"(f.x), "=f"(f.y) : "l"(a)); return f;
}
__device__ __forceinline__ float ex2f(float a) {
    float r; asm("ex2.approx.f32 %0, %1;" : "=f"(r) : "f"(a)); return r;
}
__device__ __forceinline__ u64 h2f2(__half2 h) {   // half2 -> packed f32x2
    float2 f = __half22float2(h);
    return pk2(f.x, f.y);
}

__global__ __launch_bounds__(T, 1)
void caps_main(float* __restrict__ out) {
    __shared__ float redv[G][NW][16];
    __shared__ float redz[G][NW];
    __shared__ float bc[G * 16];

    const int o   = blockIdx.y;
    const int b0  = blockIdx.x * G;
    const int tid = threadIdx.x;
    const int w    = tid >> 5;
    const int lane = tid & 31;
    const int rl   = tid >> 2;   // row within chunk (0..143)
    const int eg   = tid & 3;    // e-quarter

    const uint4* WoU = ((const uint4*)Wh) + (size_t)o * (NCH * 4 * T) + tid;
    const uint4* xq0 = ((const uint4*)Xh) + ((size_t)(b0 + 0) * IC + rl);
    const uint4* xq1 = ((const uint4*)Xh) + ((size_t)(b0 + 1) * IC + rl);

    // Packed priors: P2[g][c*2 + h] = f32x2 pair (e = eg*4 + 2h, +1)  (64 regs)
    u64 P2[G][NCH * 2];

    // ------- Phase 1: fp16 HFMA2 d-contraction (two depth-4 chains), no smem -------
    #pragma unroll
    for (int c = 0; c < NCH; ++c) {
        uint4 wv[4];
        #pragma unroll
        for (int j = 0; j < 4; ++j)
            wv[j] = WoU[(size_t)(c * 4 + j) * T];
        uint4 xv0 = xq0[c * RPC];
        uint4 xv1 = xq1[c * RPC];
        const __half2* x0 = (const __half2*)&xv0;   // (d0,d1)(d2,d3)(d4,d5)(d6,d7)
        const __half2* x1 = (const __half2*)&xv1;
        const __half2* wj0 = (const __half2*)&wv[0];
        const __half2* wj1 = (const __half2*)&wv[1];
        const __half2* wj2 = (const __half2*)&wv[2];
        const __half2* wj3 = (const __half2*)&wv[3];

        #pragma unroll
        for (int g = 0; g < G; ++g) {
            const __half2* xx = (g == 0) ? x0 : x1;
            // chain 1: d0..d3  (wv[0], wv[1])
            __half2 A1a = __hmul2(__low2half2(xx[0]),  wj0[0]);   // e01
            __half2 A1b = __hmul2(__low2half2(xx[0]),  wj0[1]);   // e23
            A1a = __hfma2(__high2half2(xx[0]), wj0[2], A1a);
            A1b = __hfma2(__high2half2(xx[0]), wj0[3], A1b);
            A1a = __hfma2(__low2half2(xx[1]),  wj1[0], A1a);
            A1b = __hfma2(__low2half2(xx[1]),  wj1[1], A1b);
            A1a = __hfma2(__high2half2(xx[1]), wj1[2], A1a);
            A1b = __hfma2(__high2half2(xx[1]), wj1[3], A1b);
            // chain 2: d4..d7  (wv[2], wv[3])
            __half2 A2a = __hmul2(__low2half2(xx[2]),  wj2[0]);
            __half2 A2b = __hmul2(__low2half2(xx[2]),  wj2[1]);
            A2a = __hfma2(__high2half2(xx[2]), wj2[2], A2a);
            A2b = __hfma2(__high2half2(xx[2]), wj2[3], A2b);
            A2a = __hfma2(__low2half2(xx[3]),  wj3[0], A2a);
            A2b = __hfma2(__low2half2(xx[3]),  wj3[1], A2b);
            A2a = __hfma2(__high2half2(xx[3]), wj3[2], A2a);
            A2b = __hfma2(__high2half2(xx[3]), wj3[3], A2b);
            // combine chains in fp32 (packed)
            P2[g][c*2+0] = add2(h2f2(A1a), h2f2(A2a));
            P2[g][c*2+1] = add2(h2f2(A1b), h2f2(A2b));
        }
    }

    // ---------------- Phase 2: routing, both g at once ----------------
    // ---- iteration 0 (uniform): s = mean_i priors (recomputed from P2) ----
    {
        const u64 ONE2 = pk2(1.f, 1.f);
        float q[G][4];
        #pragma unroll
        for (int g = 0; g < G; ++g) {
            u64 V0 = 0, V1 = 0;
            #pragma unroll
            for (int c = 0; c < NCH; ++c) {
                fma2(V0, P2[g][c*2+0], ONE2);
                fma2(V1, P2[g][c*2+1], ONE2);
            }
            float2 f;
            f = up2(V0); q[g][0] = f.x; q[g][1] = f.y;
            f = up2(V1); q[g][2] = f.x; q[g][3] = f.y;
        }
        #pragma unroll
        for (int off = 16; off >= 4; off >>= 1)
            #pragma unroll
            for (int g = 0; g < G; ++g)
                #pragma unroll
                for (int j = 0; j < 4; ++j)
                    q[g][j] += __shfl_down_sync(0xFFFFFFFFu, q[g][j], off);
        if (lane < 4)
            #pragma unroll
            for (int g = 0; g < G; ++g)
                #pragma unroll
                for (int j = 0; j < 4; ++j)
                    redv[g][w][lane * 4 + j] = q[g][j];
        __syncthreads();
        if (tid < G * 16) {
            const int g = tid >> 4;
            float s = 0.f;
            #pragma unroll
            for (int kk = 0; kk < NW; ++kk) s += redv[g][kk][tid & 15];
            s *= (1.f / (float)IC);
            float sq = s * s;
            sq += __shfl_xor_sync(0xFFFFFFFFu, sq, 1);
            sq += __shfl_xor_sync(0xFFFFFFFFu, sq, 2);
            sq += __shfl_xor_sync(0xFFFFFFFFu, sq, 4);
            sq += __shfl_xor_sync(0xFFFFFFFFu, sq, 8);
            float sc = sqrtf(sq) / (1.f + sq);
            bc[tid] = s * sc;
        }
        __syncthreads();
    }

    // ---- iterations 1,2: telescoped logits + ex2 (log2e folded into op) ----
    float opf[G][4];
    #pragma unroll
    for (int g = 0; g < G; ++g)
        #pragma unroll
        for (int j = 0; j < 4; ++j) opf[g][j] = 0.f;

    #pragma unroll
    for (int iter = 1; iter <= 2; ++iter) {
        u64 OP[G][2];
        #pragma unroll
        for (int g = 0; g < G; ++g) {
            #pragma unroll
            for (int j = 0; j < 4; ++j)
                opf[g][j] = fmaf(bc[g * 16 + eg * 4 + j], LOG2E, opf[g][j]);
            OP[g][0] = pk2(opf[g][0], opf[g][1]);
            OP[g][1] = pk2(opf[g][2], opf[g][3]);
        }

        u64 S00 = 0, S01 = 0, S10 = 0, S11 = 0;
        float vz0 = 0.f, vz1 = 0.f;
        #pragma unroll
        for (int c = 0; c < NCH; ++c) {
            u64 D0 = 0, D1 = 0;
            fma2(D0, P2[0][c*2+0], OP[0][0]); fma2(D0, P2[0][c*2+1], OP[0][1]);
            fma2(D1, P2[1][c*2+0], OP[1][0]); fma2(D1, P2[1][c*2+1], OP[1][1]);
            float2 f0 = up2(D0), f1 = up2(D1);
            float dp0 = f0.x + f0.y;
            float dp1 = f1.x + f1.y;
            dp0 += __shfl_xor_sync(0xFFFFFFFFu, dp0, 1);
            dp1 += __shfl_xor_sync(0xFFFFFFFFu, dp1, 1);
            dp0 += __shfl_xor_sync(0xFFFFFFFFu, dp0, 2);
            dp1 += __shfl_xor_sync(0xFFFFFFFFu, dp1, 2);
            float p0 = ex2f(dp0);
            float p1 = ex2f(dp1);
            vz0 += p0; vz1 += p1;
            u64 PP0 = pk2(p0, p0), PP1 = pk2(p1, p1);
            fma2(S00, P2[0][c*2+0], PP0); fma2(S01, P2[0][c*2+1], PP0);
            fma2(S10, P2[1][c*2+0], PP1); fma2(S11, P2[1][c*2+1], PP1);
        }
        float s[G][4];
        float2 f;
        f = up2(S00); s[0][0] = f.x; s[0][1] = f.y;
        f = up2(S01); s[0][2] = f.x; s[0][3] = f.y;
        f = up2(S10); s[1][0] = f.x; s[1][1] = f.y;
        f = up2(S11); s[1][2] = f.x; s[1][3] = f.y;
        float vz[G] = {vz0, vz1};
        #pragma unroll
        for (int off = 16; off >= 4; off >>= 1) {
            #pragma unroll
            for (int g = 0; g < G; ++g) {
                #pragma unroll
                for (int j = 0; j < 4; ++j)
                    s[g][j] += __shfl_down_sync(0xFFFFFFFFu, s[g][j], off);
                vz[g] += __shfl_down_sync(0xFFFFFFFFu, vz[g], off);
            }
        }
        if (lane < 4) {
            #pragma unroll
            for (int g = 0; g < G; ++g) {
                #pragma unroll
                for (int j = 0; j < 4; ++j)
                    redv[g][w][lane * 4 + j] = s[g][j];
                if (lane == 0) redz[g][w] = vz[g];
            }
        }
        __syncthreads();
        if (tid < G * 16) {
            const int g = tid >> 4;
            float sv = 0.f, Z = 0.f;
            #pragma unroll
            for (int kk = 0; kk < NW; ++kk) {
                sv += redv[g][kk][tid & 15];
                Z  += redz[g][kk];
            }
            sv *= (1.f / Z);
            float sq = sv * sv;
            sq += __shfl_xor_sync(0xFFFFFFFFu, sq, 1);
            sq += __shfl_xor_sync(0xFFFFFFFFu, sq, 2);
            sq += __shfl_xor_sync(0xFFFFFFFFu, sq, 4);
            sq += __shfl_xor_sync(0xFFFFFFFFu, sq, 8);
            float sc = sqrtf(sq) / (1.f + sq);
            bc[tid] = sv * sc;
        }
        __syncthreads();
    }

    // final output: out[o, b0+g, 0, 0, e]
    if (tid < G * 16)
        out[((size_t)o * BT + (b0 + (tid >> 4))) * EC + (tid & 15)] = bc[tid];
}

extern "C" void kernel_launch(void* const* d_in, const int* in_sizes, int n_in,
                              void* d_out, int out_size) {
    const float* x = (const float*)d_in[0];   // [512,1152,8]
    const float* W = (const float*)d_in[1];   // [10,1152,8,16]
    float* out = (float*)d_out;               // [10,512,1,1,16]

    prep_w<<<720, 256>>>(W);
    prep_x<<<2304, 256>>>(x);

    dim3 grid(BT / G, OC);
    caps_main<<<grid, T>>>(out);
}